// round 15
// baseline (speedup 1.0000x reference)
#include <cuda_runtime.h>
#include <cuda_fp16.h>
#include <cstdint>

#define N_SRC 50000
#define N_DST 50000
#define NE    800000
#define FIN   128
#define NEG_SLOPE 0.2f

#define NBLK 296         // persistent blocks; == 2 CTAs/SM guaranteed co-resident
#define NCH256 196       // ceil(50000/256) scan chunks

// ---------------------------------------------------------------------------
// Scratch (__device__ globals; no runtime allocation allowed)
// ---------------------------------------------------------------------------
__device__ __half g_m_h[(size_t)NE * FIN];     // per-edge messages (fp16), CSR order
__device__ __half g_ps_h[(size_t)N_SRC * FIN]; // fp16(src_feat @ W_src[:128])
__device__ float g_nh[(size_t)N_DST * FIN];    // dst_feat @ W_dst
__device__ int   g_deg[N_DST];                 // zeroed at load; re-zeroed by aggregate
__device__ int   g_off[N_DST + 1];
__device__ int   g_cursor[N_DST];
__device__ int   g_edges[NE];                  // edge ids grouped by dst (CSR)
__device__ int   g_bsum[256];                  // per-chunk sums for the scan
__device__ unsigned g_bar_cnt;                 // software grid barrier state
__device__ volatile unsigned g_bar_gen;        // (monotonic across replays)

// ---------------------------------------------------------------------------
// Software grid barrier: safe because all NBLK CTAs are co-resident
// (__launch_bounds__(256,2), smem fits exactly 2 CTAs/SM, NBLK = 2*148).
// ---------------------------------------------------------------------------
__device__ __forceinline__ void grid_barrier() {
    __syncthreads();
    if (threadIdx.x == 0) {
        __threadfence();
        unsigned gen = g_bar_gen;
        if (atomicAdd(&g_bar_cnt, 1) == NBLK - 1) {
            atomicExch(&g_bar_cnt, 0);
            __threadfence();
            g_bar_gen = gen + 1;
        } else {
            while (g_bar_gen == gen) { }
            __threadfence();
        }
    }
    __syncthreads();
}

// ---------------------------------------------------------------------------
// Warp MMA helpers
// ---------------------------------------------------------------------------
__device__ __forceinline__ void mma_f16(float* c, const uint32_t* a, const uint32_t* b) {
    asm volatile(
        "mma.sync.aligned.m16n8k16.row.col.f32.f16.f16.f32 "
        "{%0,%1,%2,%3}, {%4,%5,%6,%7}, {%8,%9}, {%0,%1,%2,%3};\n"
        : "+f"(c[0]), "+f"(c[1]), "+f"(c[2]), "+f"(c[3])
        : "r"(a[0]), "r"(a[1]), "r"(a[2]), "r"(a[3]),
          "r"(b[0]), "r"(b[1]));
}
__device__ __forceinline__ uint32_t pack_f16x2(float lo, float hi) {
    uint32_t d;
    asm("cvt.rn.f16x2.f32 %0, %1, %2;" : "=r"(d) : "f"(hi), "f"(lo));
    return d;
}

// ---------------------------------------------------------------------------
// SMEM geometry (stride 136 halves -> conflict-free fragment pattern)
// ---------------------------------------------------------------------------
#define AS 136
#define TILE_H (128 * AS)
#define OFF_A  0
#define OFF_B  TILE_H                  // edge kernel: single B tile
#define OFF_B0 TILE_H                  // prologue: W_top tile
#define OFF_B1 (2 * TILE_H)            // prologue: W_dst tile
#define SMEM_EDGE (2 * TILE_H * 2)     // 69632 B  -> 2 CTAs/SM
#define SMEM_NODE (3 * TILE_H * 2)     // 104448 B -> 2 CTAs/SM (208.9KB < 228KB)

// ---------------------------------------------------------------------------
// Fused prologue (one launch, persistent, software grid barriers):
//   Phase 1: node projections (warps 0-6) + degree histogram (warp 7)
//   Phase 2: 3-step exclusive scan of g_deg -> g_off/g_cursor
//   Phase 3: CSR fill -> g_edges
// ---------------------------------------------------------------------------
__global__ __launch_bounds__(256, 2)
void prologue_kernel(const float* __restrict__ src_feat,
                     const float* __restrict__ dst_feat,
                     const float* __restrict__ W_top,
                     const float* __restrict__ W_dst,
                     const int* __restrict__ dst_idx)
{
    extern __shared__ __half smh[];
    int* sints = (int*)smh;              // reused as int scratch in scan phases

    const int tid  = threadIdx.x;
    const int wid  = tid >> 5;
    const int lane = tid & 31;
    const int g    = lane >> 2;
    const int tg   = lane & 3;
    const int abase = OFF_A + wid * 16 * AS;

    // ---- Phase 1 prep: convert both weight tiles: B[n][k] = fp16(W[k][n]) --
    for (int s = tid; s < 128 * 32; s += 256) {
        int k  = s >> 5;
        int n0 = (s & 31) << 2;
        float4 v0 = *(const float4*)&W_top[k * FIN + n0];
        float4 v1 = *(const float4*)&W_dst[k * FIN + n0];
        smh[OFF_B0 + (n0 + 0) * AS + k] = __float2half_rn(v0.x);
        smh[OFF_B0 + (n0 + 1) * AS + k] = __float2half_rn(v0.y);
        smh[OFF_B0 + (n0 + 2) * AS + k] = __float2half_rn(v0.z);
        smh[OFF_B0 + (n0 + 3) * AS + k] = __float2half_rn(v0.w);
        smh[OFF_B1 + (n0 + 0) * AS + k] = __float2half_rn(v1.x);
        smh[OFF_B1 + (n0 + 1) * AS + k] = __float2half_rn(v1.y);
        smh[OFF_B1 + (n0 + 2) * AS + k] = __float2half_rn(v1.z);
        smh[OFF_B1 + (n0 + 3) * AS + k] = __float2half_rn(v1.w);
    }
    __syncthreads();

    // ---- Phase 1: GEMM warps (0-6) + histogram warp (7) --------------------
    if (wid == 7) {
        const int4* d4 = (const int4*)dst_idx;
        const int n4 = NE / 4;
        for (int i = blockIdx.x * 32 + lane; i < n4; i += gridDim.x * 32) {
            int4 v = d4[i];
            atomicAdd(&g_deg[v.x], 1);
            atomicAdd(&g_deg[v.y], 1);
            atomicAdd(&g_deg[v.z], 1);
            atomicAdd(&g_deg[v.w], 1);
        }
    } else {
        const int psch = N_SRC >> 4;         // 3125
        const int nch  = psch * 2;           // 6250
        const int gstep = gridDim.x * 7;

        for (int c = blockIdx.x * 7 + wid; c < nch; c += gstep) {
            const bool isPS = (c < psch);
            const float* __restrict__ A = isPS ? src_feat : dst_feat;
            const int row0 = (isPS ? c : c - psch) << 4;
            const int boff = isPS ? OFF_B0 : OFF_B1;

            #pragma unroll 4
            for (int p = 0; p < 16; p++) {
                float4 v = *(const float4*)&A[(size_t)(row0 + p) * FIN + (lane << 2)];
                *(uint2*)&smh[abase + p * AS + (lane << 2)] =
                    make_uint2(pack_f16x2(v.x, v.y), pack_f16x2(v.z, v.w));
            }
            __syncwarp();

            float acc[16][4];
            #pragma unroll
            for (int ni = 0; ni < 16; ni++)
                #pragma unroll
                for (int q = 0; q < 4; q++) acc[ni][q] = 0.f;

            #pragma unroll
            for (int ks = 0; ks < 8; ks++) {
                const int kc = ks * 16 + tg * 2;
                uint32_t af[4];
                int rbase = abase + g * AS + kc;
                af[0] = *(const uint32_t*)&smh[rbase];
                af[1] = *(const uint32_t*)&smh[rbase + 8 * AS];
                af[2] = *(const uint32_t*)&smh[rbase + 8];
                af[3] = *(const uint32_t*)&smh[rbase + 8 * AS + 8];
                #pragma unroll
                for (int ni = 0; ni < 16; ni++) {
                    int nbase = boff + (ni * 8 + g) * AS + kc;
                    uint32_t bf[2];
                    bf[0] = *(const uint32_t*)&smh[nbase];
                    bf[1] = *(const uint32_t*)&smh[nbase + 8];
                    mma_f16(acc[ni], af, bf);
                }
            }

            const int gra = row0 + g;
            const int grb = gra + 8;
            if (isPS) {
                #pragma unroll
                for (int ni = 0; ni < 16; ni++) {
                    int col = ni * 8 + tg * 2;
                    *(uint32_t*)&g_ps_h[(size_t)gra * FIN + col] = pack_f16x2(acc[ni][0], acc[ni][1]);
                    *(uint32_t*)&g_ps_h[(size_t)grb * FIN + col] = pack_f16x2(acc[ni][2], acc[ni][3]);
                }
            } else {
                #pragma unroll
                for (int ni = 0; ni < 16; ni++) {
                    int col = ni * 8 + tg * 2;
                    *(float2*)&g_nh[(size_t)gra * FIN + col] = make_float2(acc[ni][0], acc[ni][1]);
                    *(float2*)&g_nh[(size_t)grb * FIN + col] = make_float2(acc[ni][2], acc[ni][3]);
                }
            }
            __syncwarp();
        }
    }

    grid_barrier();   // g_deg complete

    // ---- Phase 2a: block-local inclusive scan of 256-chunks ----------------
    if (blockIdx.x < NCH256) {
        int i = blockIdx.x * 256 + tid;
        int v = (i < N_DST) ? g_deg[i] : 0;
        sints[tid] = v;
        __syncthreads();
        #pragma unroll
        for (int o = 1; o < 256; o <<= 1) {
            int tmp = (tid >= o) ? sints[tid - o] : 0;
            __syncthreads();
            sints[tid] += tmp;
            __syncthreads();
        }
        if (i < N_DST) g_off[i] = sints[tid] - v;       // local exclusive
        if (tid == 255) g_bsum[blockIdx.x] = sints[255]; // chunk total
    }

    grid_barrier();   // g_bsum complete

    // ---- Phase 2b: block 0 scans the chunk sums ----------------------------
    if (blockIdx.x == 0) {
        int v = (tid < NCH256) ? g_bsum[tid] : 0;
        sints[tid] = v;
        __syncthreads();
        #pragma unroll
        for (int o = 1; o < 256; o <<= 1) {
            int tmp = (tid >= o) ? sints[tid - o] : 0;
            __syncthreads();
            sints[tid] += tmp;
            __syncthreads();
        }
        if (tid < NCH256) g_bsum[tid] = sints[tid] - v; // exclusive
        if (tid == 0) g_off[N_DST] = sints[255];        // total = NE
    }

    grid_barrier();   // chunk prefixes complete

    // ---- Phase 2c: add chunk prefix -> final g_off / g_cursor --------------
    if (blockIdx.x < NCH256) {
        int i = blockIdx.x * 256 + tid;
        if (i < N_DST) {
            int ex = g_off[i] + g_bsum[blockIdx.x];
            g_off[i]    = ex;
            g_cursor[i] = ex;
        }
    }

    grid_barrier();   // g_cursor final

    // ---- Phase 3: CSR fill (grid-stride) -----------------------------------
    for (int e = blockIdx.x * 256 + tid; e < NE; e += gridDim.x * 256) {
        int p = atomicAdd(&g_cursor[dst_idx[e]], 1);
        g_edges[p] = e;
    }
}

// ---------------------------------------------------------------------------
// Edge GEMM (unchanged): warp-autonomous, idx-prefetched,
// m[j] = fp16( edge_feat[g_edges[j]] @ W_edge + ps_h[src_idx[g_edges[j]]] )
// ---------------------------------------------------------------------------
__global__ __launch_bounds__(256, 2)
void edge_gemm_kernel(const float* __restrict__ A, const float* __restrict__ W,
                      const int* __restrict__ src_idx)
{
    extern __shared__ __half smh[];

    const int tid  = threadIdx.x;
    const int wid  = tid >> 5;
    const int lane = tid & 31;
    const int g    = lane >> 2;
    const int tg   = lane & 3;
    const int abase = OFF_A + wid * 16 * AS;

    for (int s = tid; s < 128 * 32; s += 256) {
        int k  = s >> 5;
        int n0 = (s & 31) << 2;
        float4 v = *(const float4*)&W[k * FIN + n0];
        smh[OFF_B + (n0 + 0) * AS + k] = __float2half_rn(v.x);
        smh[OFF_B + (n0 + 1) * AS + k] = __float2half_rn(v.y);
        smh[OFF_B + (n0 + 2) * AS + k] = __float2half_rn(v.z);
        smh[OFF_B + (n0 + 3) * AS + k] = __float2half_rn(v.w);
    }
    __syncthreads();

    const int nchunks = NE >> 4;
    const int gstep   = gridDim.x * 8;
    int c = blockIdx.x * 8 + wid;

    int are = 0, sreg = 0;
    if (c < nchunks && lane < 16) {
        are  = g_edges[(c << 4) + lane];
        sreg = src_idx[are];
    }

    while (c < nchunks) {
        const int row0 = c << 4;
        const int areC  = are;
        const int sregC = sreg;

        #pragma unroll 4
        for (int p = 0; p < 16; p++) {
            int ar = __shfl_sync(0xffffffffu, areC, p);
            float4 v = *(const float4*)&A[(size_t)ar * FIN + (lane << 2)];
            *(uint2*)&smh[abase + p * AS + (lane << 2)] =
                make_uint2(pack_f16x2(v.x, v.y), pack_f16x2(v.z, v.w));
        }
        __syncwarp();

        const int cn = c + gstep;
        if (cn < nchunks && lane < 16) {
            are  = g_edges[(cn << 4) + lane];
            sreg = src_idx[are];
        }

        float acc[16][4];
        #pragma unroll
        for (int ni = 0; ni < 16; ni++)
            #pragma unroll
            for (int q = 0; q < 4; q++) acc[ni][q] = 0.f;

        #pragma unroll
        for (int ks = 0; ks < 8; ks++) {
            const int kc = ks * 16 + tg * 2;
            uint32_t af[4];
            int rbase = abase + g * AS + kc;
            af[0] = *(const uint32_t*)&smh[rbase];
            af[1] = *(const uint32_t*)&smh[rbase + 8 * AS];
            af[2] = *(const uint32_t*)&smh[rbase + 8];
            af[3] = *(const uint32_t*)&smh[rbase + 8 * AS + 8];
            #pragma unroll
            for (int ni = 0; ni < 16; ni++) {
                int nbase = OFF_B + (ni * 8 + g) * AS + kc;
                uint32_t bf[2];
                bf[0] = *(const uint32_t*)&smh[nbase];
                bf[1] = *(const uint32_t*)&smh[nbase + 8];
                mma_f16(acc[ni], af, bf);
            }
        }

        const int gra = row0 + g;
        const int grb = gra + 8;
        int sa = __shfl_sync(0xffffffffu, sregC, g);
        int sb = __shfl_sync(0xffffffffu, sregC, g + 8);
        #pragma unroll
        for (int ni = 0; ni < 16; ni++) {
            int col = ni * 8 + tg * 2;
            uint32_t pr0 = *(const uint32_t*)&g_ps_h[(size_t)sa * FIN + col];
            uint32_t pr1 = *(const uint32_t*)&g_ps_h[(size_t)sb * FIN + col];
            float2 p0 = __half22float2(*(__half2*)&pr0);
            float2 p1 = __half22float2(*(__half2*)&pr1);
            *(uint32_t*)&g_m_h[(size_t)gra * FIN + col] = pack_f16x2(acc[ni][0] + p0.x, acc[ni][1] + p0.y);
            *(uint32_t*)&g_m_h[(size_t)grb * FIN + col] = pack_f16x2(acc[ni][2] + p1.x, acc[ni][3] + p1.y);
        }
        __syncwarp();
        c = cn;
    }
}

// ---------------------------------------------------------------------------
// Aggregation (hot loop) + g_deg re-zero for the next graph replay
// ---------------------------------------------------------------------------
__device__ __forceinline__ float lrelu(float x) { return x > 0.f ? x : NEG_SLOPE * x; }

__global__ void aggregate_kernel(const float* __restrict__ bias, float* __restrict__ out)
{
    int gt = blockIdx.x * blockDim.x + threadIdx.x;
    if (gt < N_DST) g_deg[gt] = 0;    // reset for next replay (g_deg no longer needed)

    int warp = gt >> 5;
    int lane = threadIdx.x & 31;
    if (warp >= N_DST) return;
    const int d = warp;

    float4 nh = ((const float4*)g_nh)[(size_t)d * 32 + lane];
    float4 num = make_float4(0.f, 0.f, 0.f, 0.f);
    float4 den = make_float4(0.f, 0.f, 0.f, 0.f);

    const int beg = g_off[d];
    const int end = g_off[d + 1];
    int j = beg;
    for (; j + 2 <= end; j += 2) {
        uint2 mr0 = *(const uint2*)&g_m_h[(size_t)j * FIN + lane * 4];
        uint2 mr1 = *(const uint2*)&g_m_h[(size_t)(j + 1) * FIN + lane * 4];
        float2 a01 = __half22float2(*(__half2*)&mr0.x);
        float2 a23 = __half22float2(*(__half2*)&mr0.y);
        float2 b01 = __half22float2(*(__half2*)&mr1.x);
        float2 b23 = __half22float2(*(__half2*)&mr1.y);
        float ex;
        ex = __expf(lrelu(a01.x + nh.x)); num.x += a01.x * ex; den.x += ex;
        ex = __expf(lrelu(a01.y + nh.y)); num.y += a01.y * ex; den.y += ex;
        ex = __expf(lrelu(a23.x + nh.z)); num.z += a23.x * ex; den.z += ex;
        ex = __expf(lrelu(a23.y + nh.w)); num.w += a23.y * ex; den.w += ex;
        ex = __expf(lrelu(b01.x + nh.x)); num.x += b01.x * ex; den.x += ex;
        ex = __expf(lrelu(b01.y + nh.y)); num.y += b01.y * ex; den.y += ex;
        ex = __expf(lrelu(b23.x + nh.z)); num.z += b23.x * ex; den.z += ex;
        ex = __expf(lrelu(b23.y + nh.w)); num.w += b23.y * ex; den.w += ex;
    }
    if (j < end) {
        uint2 mr0 = *(const uint2*)&g_m_h[(size_t)j * FIN + lane * 4];
        float2 a01 = __half22float2(*(__half2*)&mr0.x);
        float2 a23 = __half22float2(*(__half2*)&mr0.y);
        float ex;
        ex = __expf(lrelu(a01.x + nh.x)); num.x += a01.x * ex; den.x += ex;
        ex = __expf(lrelu(a01.y + nh.y)); num.y += a01.y * ex; den.y += ex;
        ex = __expf(lrelu(a23.x + nh.z)); num.z += a23.x * ex; den.z += ex;
        ex = __expf(lrelu(a23.y + nh.w)); num.w += a23.y * ex; den.w += ex;
    }

    float4 b4 = ((const float4*)bias)[lane];
    float4 o;
    o.x = (den.x > 0.f) ? num.x / den.x + b4.x : b4.x;
    o.y = (den.y > 0.f) ? num.y / den.y + b4.y : b4.y;
    o.z = (den.z > 0.f) ? num.z / den.z + b4.z : b4.z;
    o.w = (den.w > 0.f) ? num.w / den.w + b4.w : b4.w;
    ((float4*)out)[(size_t)d * 32 + lane] = o;
}

// ---------------------------------------------------------------------------
// Launch: 3 kernels total
// ---------------------------------------------------------------------------
extern "C" void kernel_launch(void* const* d_in, const int* in_sizes, int n_in,
                              void* d_out, int out_size)
{
    const float* src_feat  = (const float*)d_in[0];
    const float* dst_feat  = (const float*)d_in[1];
    const float* edge_feat = (const float*)d_in[2];
    const float* W_src     = (const float*)d_in[3];   // [256,128]
    const float* W_dst     = (const float*)d_in[4];   // [128,128]
    const float* bias      = (const float*)d_in[5];   // [128]
    const int*   src_idx   = (const int*)d_in[6];
    const int*   dst_idx   = (const int*)d_in[7];
    float* out = (float*)d_out;

    const float* W_top  = W_src;              // rows 0..127  (src part)
    const float* W_edge = W_src + 128 * FIN;  // rows 128..255 (edge part)

    cudaFuncSetAttribute(prologue_kernel,  cudaFuncAttributeMaxDynamicSharedMemorySize, SMEM_NODE);
    cudaFuncSetAttribute(edge_gemm_kernel, cudaFuncAttributeMaxDynamicSharedMemorySize, SMEM_EDGE);

    // 1) node projections + histogram + scan + CSR fill (persistent, grid barriers)
    prologue_kernel<<<NBLK, 256, SMEM_NODE>>>(src_feat, dst_feat, W_top, W_dst, dst_idx);

    // 2) edge messages in CSR order
    edge_gemm_kernel<<<NBLK, 256, SMEM_EDGE>>>(edge_feat, W_edge, src_idx);

    // 3) segment softmax + weighted aggregation (+ g_deg reset for next replay)
    aggregate_kernel<<<(N_DST * 32 + 255) / 256, 256>>>(bias, out);
}

// round 17
// speedup vs baseline: 1.1043x; 1.1043x over previous
#include <cuda_runtime.h>
#include <cuda_fp16.h>
#include <cstdint>

#define N_SRC 50000
#define N_DST 50000
#define NE    800000
#define FIN   128
#define NEG_SLOPE 0.2f

#define SCAN_BLOCKS 49   // ceil(50000/1024)
#define NBLK 296         // persistent blocks (2 CTAs/SM)

// ---------------------------------------------------------------------------
// Scratch (__device__ globals; no runtime allocation allowed)
// ---------------------------------------------------------------------------
__device__ __half g_m_h[(size_t)NE * FIN];     // per-edge messages (fp16), CSR order
__device__ __half g_ps_h[(size_t)N_SRC * FIN]; // fp16(src_feat @ W_src[:128])
__device__ float g_nh[(size_t)N_DST * FIN];    // dst_feat @ W_dst
__device__ int   g_deg[N_DST];                 // zeroed at load; re-zeroed by aggregate
__device__ int   g_off[N_DST + 1];
__device__ int   g_cursor[N_DST];
__device__ int   g_edges[NE];                  // edge ids grouped by dst (CSR)
__device__ int   g_bsum[64];                   // per-block sums for the scan

// ---------------------------------------------------------------------------
// Warp MMA helpers
// ---------------------------------------------------------------------------
__device__ __forceinline__ void mma_f16(float* c, const uint32_t* a, const uint32_t* b) {
    asm volatile(
        "mma.sync.aligned.m16n8k16.row.col.f32.f16.f16.f32 "
        "{%0,%1,%2,%3}, {%4,%5,%6,%7}, {%8,%9}, {%0,%1,%2,%3};\n"
        : "+f"(c[0]), "+f"(c[1]), "+f"(c[2]), "+f"(c[3])
        : "r"(a[0]), "r"(a[1]), "r"(a[2]), "r"(a[3]),
          "r"(b[0]), "r"(b[1]));
}
__device__ __forceinline__ uint32_t pack_f16x2(float lo, float hi) {
    uint32_t d;
    asm("cvt.rn.f16x2.f32 %0, %1, %2;" : "=r"(d) : "f"(hi), "f"(lo));
    return d;
}

// ---------------------------------------------------------------------------
// SMEM geometry (stride 136 halves -> conflict-free fragment pattern)
// ---------------------------------------------------------------------------
#define AS 136
#define TILE_H (128 * AS)
#define OFF_A  0
#define OFF_B  TILE_H                  // edge kernel: single B tile
#define OFF_B0 TILE_H                  // node kernel: W_top tile
#define OFF_B1 (2 * TILE_H)            // node kernel: W_dst tile
#define SMEM_EDGE (2 * TILE_H * 2)     // 69632 B  -> 2 CTAs/SM
#define SMEM_NODE (3 * TILE_H * 2)     // 104448 B -> 2 CTAs/SM (208.9KB < 228KB)

// ---------------------------------------------------------------------------
// Fused kernel: node projections (warps 0-6) + degree histogram (warp 7).
// ---------------------------------------------------------------------------
__global__ __launch_bounds__(256, 2)
void node_hist_kernel(const float* __restrict__ src_feat,
                      const float* __restrict__ dst_feat,
                      const float* __restrict__ W_top,
                      const float* __restrict__ W_dst,
                      const int* __restrict__ dst_idx)
{
    extern __shared__ __half smh[];

    const int tid  = threadIdx.x;
    const int wid  = tid >> 5;
    const int lane = tid & 31;
    const int g    = lane >> 2;
    const int tg   = lane & 3;
    const int abase = OFF_A + wid * 16 * AS;

    // Convert both weight tiles: B[n][k] = fp16(W[k][n])
    for (int s = tid; s < 128 * 32; s += 256) {
        int k  = s >> 5;
        int n0 = (s & 31) << 2;
        float4 v0 = *(const float4*)&W_top[k * FIN + n0];
        float4 v1 = *(const float4*)&W_dst[k * FIN + n0];
        smh[OFF_B0 + (n0 + 0) * AS + k] = __float2half_rn(v0.x);
        smh[OFF_B0 + (n0 + 1) * AS + k] = __float2half_rn(v0.y);
        smh[OFF_B0 + (n0 + 2) * AS + k] = __float2half_rn(v0.z);
        smh[OFF_B0 + (n0 + 3) * AS + k] = __float2half_rn(v0.w);
        smh[OFF_B1 + (n0 + 0) * AS + k] = __float2half_rn(v1.x);
        smh[OFF_B1 + (n0 + 1) * AS + k] = __float2half_rn(v1.y);
        smh[OFF_B1 + (n0 + 2) * AS + k] = __float2half_rn(v1.z);
        smh[OFF_B1 + (n0 + 3) * AS + k] = __float2half_rn(v1.w);
    }
    __syncthreads();

    if (wid == 7) {
        // Histogram warp: int4-vectorized, hidden under GEMM warps' MMA time
        const int4* d4 = (const int4*)dst_idx;
        const int n4 = NE / 4;
        for (int i = blockIdx.x * 32 + lane; i < n4; i += gridDim.x * 32) {
            int4 v = d4[i];
            atomicAdd(&g_deg[v.x], 1);
            atomicAdd(&g_deg[v.y], 1);
            atomicAdd(&g_deg[v.z], 1);
            atomicAdd(&g_deg[v.w], 1);
        }
        return;
    }

    // GEMM warps (7 per block): combined ps+nh chunk stream
    const int psch = N_SRC >> 4;         // 3125
    const int nch  = psch * 2;           // 6250
    const int gstep = gridDim.x * 7;

    for (int c = blockIdx.x * 7 + wid; c < nch; c += gstep) {
        const bool isPS = (c < psch);
        const float* __restrict__ A = isPS ? src_feat : dst_feat;
        const int row0 = (isPS ? c : c - psch) << 4;
        const int boff = isPS ? OFF_B0 : OFF_B1;

        #pragma unroll 4
        for (int p = 0; p < 16; p++) {
            float4 v = *(const float4*)&A[(size_t)(row0 + p) * FIN + (lane << 2)];
            *(uint2*)&smh[abase + p * AS + (lane << 2)] =
                make_uint2(pack_f16x2(v.x, v.y), pack_f16x2(v.z, v.w));
        }
        __syncwarp();

        float acc[16][4];
        #pragma unroll
        for (int ni = 0; ni < 16; ni++)
            #pragma unroll
            for (int q = 0; q < 4; q++) acc[ni][q] = 0.f;

        #pragma unroll
        for (int ks = 0; ks < 8; ks++) {
            const int kc = ks * 16 + tg * 2;
            uint32_t af[4];
            int rbase = abase + g * AS + kc;
            af[0] = *(const uint32_t*)&smh[rbase];
            af[1] = *(const uint32_t*)&smh[rbase + 8 * AS];
            af[2] = *(const uint32_t*)&smh[rbase + 8];
            af[3] = *(const uint32_t*)&smh[rbase + 8 * AS + 8];
            #pragma unroll
            for (int ni = 0; ni < 16; ni++) {
                int nbase = boff + (ni * 8 + g) * AS + kc;
                uint32_t bf[2];
                bf[0] = *(const uint32_t*)&smh[nbase];
                bf[1] = *(const uint32_t*)&smh[nbase + 8];
                mma_f16(acc[ni], af, bf);
            }
        }

        const int gra = row0 + g;
        const int grb = gra + 8;
        if (isPS) {
            #pragma unroll
            for (int ni = 0; ni < 16; ni++) {
                int col = ni * 8 + tg * 2;
                *(uint32_t*)&g_ps_h[(size_t)gra * FIN + col] = pack_f16x2(acc[ni][0], acc[ni][1]);
                *(uint32_t*)&g_ps_h[(size_t)grb * FIN + col] = pack_f16x2(acc[ni][2], acc[ni][3]);
            }
        } else {
            #pragma unroll
            for (int ni = 0; ni < 16; ni++) {
                int col = ni * 8 + tg * 2;
                *(float2*)&g_nh[(size_t)gra * FIN + col] = make_float2(acc[ni][0], acc[ni][1]);
                *(float2*)&g_nh[(size_t)grb * FIN + col] = make_float2(acc[ni][2], acc[ni][3]);
            }
        }
        __syncwarp();
    }
}

// ---------------------------------------------------------------------------
// Scan phases
// ---------------------------------------------------------------------------
__global__ void block_reduce_kernel() {
    __shared__ int sw[32];
    int i = blockIdx.x * 1024 + threadIdx.x;
    int lane = threadIdx.x & 31;
    int wid  = threadIdx.x >> 5;
    int s = (i < N_DST) ? g_deg[i] : 0;
    #pragma unroll
    for (int o = 16; o > 0; o >>= 1) s += __shfl_down_sync(0xffffffffu, s, o);
    if (lane == 0) sw[wid] = s;
    __syncthreads();
    if (wid == 0) {
        s = sw[lane];
        #pragma unroll
        for (int o = 16; o > 0; o >>= 1) s += __shfl_down_sync(0xffffffffu, s, o);
        if (lane == 0) g_bsum[blockIdx.x] = s;
    }
}
__global__ void scan_bsum_kernel() {
    __shared__ int sh[64];
    int t = threadIdx.x;
    int v = (t < SCAN_BLOCKS) ? g_bsum[t] : 0;
    sh[t] = v;
    __syncthreads();
    #pragma unroll
    for (int o = 1; o < 64; o <<= 1) {
        int tmp = (t >= o) ? sh[t - o] : 0;
        __syncthreads();
        sh[t] += tmp;
        __syncthreads();
    }
    if (t < SCAN_BLOCKS) g_bsum[t] = sh[t] - v;
    if (t == 0) g_off[N_DST] = sh[SCAN_BLOCKS - 1];
}
__global__ void local_scan_kernel() {
    __shared__ int sh[1024];
    int t = threadIdx.x;
    int i = blockIdx.x * 1024 + t;
    int v = (i < N_DST) ? g_deg[i] : 0;
    sh[t] = v;
    __syncthreads();
    #pragma unroll
    for (int o = 1; o < 1024; o <<= 1) {
        int tmp = (t >= o) ? sh[t - o] : 0;
        __syncthreads();
        sh[t] += tmp;
        __syncthreads();
    }
    if (i < N_DST) {
        int ex = sh[t] - v + g_bsum[blockIdx.x];
        g_off[i]    = ex;
        g_cursor[i] = ex;
    }
}
__global__ void fill_kernel(const int* __restrict__ dst_idx) {
    int e = blockIdx.x * blockDim.x + threadIdx.x;
    if (e < NE) {
        int p = atomicAdd(&g_cursor[dst_idx[e]], 1);
        g_edges[p] = e;
    }
}

// ---------------------------------------------------------------------------
// Edge GEMM: warp-autonomous, idx-prefetched + L2 data-prefetch of next rows,
// m[j] = fp16( edge_feat[g_edges[j]] @ W_edge + ps_h[src_idx[g_edges[j]]] )
// ---------------------------------------------------------------------------
__global__ __launch_bounds__(256, 2)
void edge_gemm_kernel(const float* __restrict__ A, const float* __restrict__ W,
                      const int* __restrict__ src_idx)
{
    extern __shared__ __half smh[];

    const int tid  = threadIdx.x;
    const int wid  = tid >> 5;
    const int lane = tid & 31;
    const int g    = lane >> 2;
    const int tg   = lane & 3;
    const int abase = OFF_A + wid * 16 * AS;

    for (int s = tid; s < 128 * 32; s += 256) {
        int k  = s >> 5;
        int n0 = (s & 31) << 2;
        float4 v = *(const float4*)&W[k * FIN + n0];
        smh[OFF_B + (n0 + 0) * AS + k] = __float2half_rn(v.x);
        smh[OFF_B + (n0 + 1) * AS + k] = __float2half_rn(v.y);
        smh[OFF_B + (n0 + 2) * AS + k] = __float2half_rn(v.z);
        smh[OFF_B + (n0 + 3) * AS + k] = __float2half_rn(v.w);
    }
    __syncthreads();

    const int nchunks = NE >> 4;
    const int gstep   = gridDim.x * 8;
    int c = blockIdx.x * 8 + wid;

    int are = 0, sreg = 0;
    if (c < nchunks && lane < 16) {
        are  = g_edges[(c << 4) + lane];
        sreg = src_idx[are];
    }

    while (c < nchunks) {
        const int row0 = c << 4;
        const int areC  = are;
        const int sregC = sreg;

        #pragma unroll 4
        for (int p = 0; p < 16; p++) {
            int ar = __shfl_sync(0xffffffffu, areC, p);
            float4 v = *(const float4*)&A[(size_t)ar * FIN + (lane << 2)];
            *(uint2*)&smh[abase + p * AS + (lane << 2)] =
                make_uint2(pack_f16x2(v.x, v.y), pack_f16x2(v.z, v.w));
        }
        __syncwarp();

        const int cn = c + gstep;
        if (cn < nchunks && lane < 16) {
            are  = g_edges[(cn << 4) + lane];
            sreg = src_idx[are];
        }
        // L2-prefetch next chunk's 16 rows (512B each): lanes (l, l+16)
        // cover offsets {0,128} and {256,384} of row (l & 15).
        if (cn < nchunks) {
            int arp = __shfl_sync(0xffffffffu, are, lane & 15);
            const char* pb = (const char*)&A[(size_t)arp * FIN] + (lane >> 4) * 256;
            asm volatile("prefetch.global.L2 [%0];" :: "l"(pb));
            asm volatile("prefetch.global.L2 [%0];" :: "l"(pb + 128));
        }

        float acc[16][4];
        #pragma unroll
        for (int ni = 0; ni < 16; ni++)
            #pragma unroll
            for (int q = 0; q < 4; q++) acc[ni][q] = 0.f;

        #pragma unroll
        for (int ks = 0; ks < 8; ks++) {
            const int kc = ks * 16 + tg * 2;
            uint32_t af[4];
            int rbase = abase + g * AS + kc;
            af[0] = *(const uint32_t*)&smh[rbase];
            af[1] = *(const uint32_t*)&smh[rbase + 8 * AS];
            af[2] = *(const uint32_t*)&smh[rbase + 8];
            af[3] = *(const uint32_t*)&smh[rbase + 8 * AS + 8];
            #pragma unroll
            for (int ni = 0; ni < 16; ni++) {
                int nbase = OFF_B + (ni * 8 + g) * AS + kc;
                uint32_t bf[2];
                bf[0] = *(const uint32_t*)&smh[nbase];
                bf[1] = *(const uint32_t*)&smh[nbase + 8];
                mma_f16(acc[ni], af, bf);
            }
        }

        const int gra = row0 + g;
        const int grb = gra + 8;
        int sa = __shfl_sync(0xffffffffu, sregC, g);
        int sb = __shfl_sync(0xffffffffu, sregC, g + 8);
        #pragma unroll
        for (int ni = 0; ni < 16; ni++) {
            int col = ni * 8 + tg * 2;
            uint32_t pr0 = *(const uint32_t*)&g_ps_h[(size_t)sa * FIN + col];
            uint32_t pr1 = *(const uint32_t*)&g_ps_h[(size_t)sb * FIN + col];
            float2 p0 = __half22float2(*(__half2*)&pr0);
            float2 p1 = __half22float2(*(__half2*)&pr1);
            *(uint32_t*)&g_m_h[(size_t)gra * FIN + col] = pack_f16x2(acc[ni][0] + p0.x, acc[ni][1] + p0.y);
            *(uint32_t*)&g_m_h[(size_t)grb * FIN + col] = pack_f16x2(acc[ni][2] + p1.x, acc[ni][3] + p1.y);
        }
        __syncwarp();
        c = cn;
    }
}

// ---------------------------------------------------------------------------
// Aggregation (hot loop) + g_deg re-zero for the next graph replay
// ---------------------------------------------------------------------------
__device__ __forceinline__ float lrelu(float x) { return x > 0.f ? x : NEG_SLOPE * x; }

__global__ void aggregate_kernel(const float* __restrict__ bias, float* __restrict__ out)
{
    int gt = blockIdx.x * blockDim.x + threadIdx.x;
    if (gt < N_DST) g_deg[gt] = 0;    // reset for next replay (g_deg no longer needed)

    int warp = gt >> 5;
    int lane = threadIdx.x & 31;
    if (warp >= N_DST) return;
    const int d = warp;

    float4 nh = ((const float4*)g_nh)[(size_t)d * 32 + lane];
    float4 num = make_float4(0.f, 0.f, 0.f, 0.f);
    float4 den = make_float4(0.f, 0.f, 0.f, 0.f);

    const int beg = g_off[d];
    const int end = g_off[d + 1];
    int j = beg;
    for (; j + 2 <= end; j += 2) {
        uint2 mr0 = *(const uint2*)&g_m_h[(size_t)j * FIN + lane * 4];
        uint2 mr1 = *(const uint2*)&g_m_h[(size_t)(j + 1) * FIN + lane * 4];
        float2 a01 = __half22float2(*(__half2*)&mr0.x);
        float2 a23 = __half22float2(*(__half2*)&mr0.y);
        float2 b01 = __half22float2(*(__half2*)&mr1.x);
        float2 b23 = __half22float2(*(__half2*)&mr1.y);
        float ex;
        ex = __expf(lrelu(a01.x + nh.x)); num.x += a01.x * ex; den.x += ex;
        ex = __expf(lrelu(a01.y + nh.y)); num.y += a01.y * ex; den.y += ex;
        ex = __expf(lrelu(a23.x + nh.z)); num.z += a23.x * ex; den.z += ex;
        ex = __expf(lrelu(a23.y + nh.w)); num.w += a23.y * ex; den.w += ex;
        ex = __expf(lrelu(b01.x + nh.x)); num.x += b01.x * ex; den.x += ex;
        ex = __expf(lrelu(b01.y + nh.y)); num.y += b01.y * ex; den.y += ex;
        ex = __expf(lrelu(b23.x + nh.z)); num.z += b23.x * ex; den.z += ex;
        ex = __expf(lrelu(b23.y + nh.w)); num.w += b23.y * ex; den.w += ex;
    }
    if (j < end) {
        uint2 mr0 = *(const uint2*)&g_m_h[(size_t)j * FIN + lane * 4];
        float2 a01 = __half22float2(*(__half2*)&mr0.x);
        float2 a23 = __half22float2(*(__half2*)&mr0.y);
        float ex;
        ex = __expf(lrelu(a01.x + nh.x)); num.x += a01.x * ex; den.x += ex;
        ex = __expf(lrelu(a01.y + nh.y)); num.y += a01.y * ex; den.y += ex;
        ex = __expf(lrelu(a23.x + nh.z)); num.z += a23.x * ex; den.z += ex;
        ex = __expf(lrelu(a23.y + nh.w)); num.w += a23.y * ex; den.w += ex;
    }

    float4 b4 = ((const float4*)bias)[lane];
    float4 o;
    o.x = (den.x > 0.f) ? num.x / den.x + b4.x : b4.x;
    o.y = (den.y > 0.f) ? num.y / den.y + b4.y : b4.y;
    o.z = (den.z > 0.f) ? num.z / den.z + b4.z : b4.z;
    o.w = (den.w > 0.f) ? num.w / den.w + b4.w : b4.w;
    ((float4*)out)[(size_t)d * 32 + lane] = o;
}

// ---------------------------------------------------------------------------
// Launch
// ---------------------------------------------------------------------------
extern "C" void kernel_launch(void* const* d_in, const int* in_sizes, int n_in,
                              void* d_out, int out_size)
{
    const float* src_feat  = (const float*)d_in[0];
    const float* dst_feat  = (const float*)d_in[1];
    const float* edge_feat = (const float*)d_in[2];
    const float* W_src     = (const float*)d_in[3];   // [256,128]
    const float* W_dst     = (const float*)d_in[4];   // [128,128]
    const float* bias      = (const float*)d_in[5];   // [128]
    const int*   src_idx   = (const int*)d_in[6];
    const int*   dst_idx   = (const int*)d_in[7];
    float* out = (float*)d_out;

    const float* W_top  = W_src;              // rows 0..127  (src part)
    const float* W_edge = W_src + 128 * FIN;  // rows 128..255 (edge part)

    cudaFuncSetAttribute(node_hist_kernel, cudaFuncAttributeMaxDynamicSharedMemorySize, SMEM_NODE);
    cudaFuncSetAttribute(edge_gemm_kernel, cudaFuncAttributeMaxDynamicSharedMemorySize, SMEM_EDGE);

    // 1) node projections + degree histogram (fused; hist hidden under MMA)
    node_hist_kernel<<<NBLK, 256, SMEM_NODE>>>(src_feat, dst_feat, W_top, W_dst, dst_idx);

    // 2-4) parallel 3-phase exclusive scan of degrees
    block_reduce_kernel<<<SCAN_BLOCKS, 1024>>>();
    scan_bsum_kernel<<<1, 64>>>();
    local_scan_kernel<<<SCAN_BLOCKS, 1024>>>();

    // 5) CSR fill
    fill_kernel<<<(NE + 255) / 256, 256>>>(dst_idx);

    // 6) edge messages in CSR order (+ L2 prefetch of next chunk rows)
    edge_gemm_kernel<<<NBLK, 256, SMEM_EDGE>>>(edge_feat, W_edge, src_idx);

    // 7) segment softmax + weighted aggregation (+ g_deg reset for next replay)
    aggregate_kernel<<<(N_DST * 32 + 255) / 256, 256>>>(bias, out);
}